// round 10
// baseline (speedup 1.0000x reference)
#include <cuda_runtime.h>
#include <math.h>
#include <float.h>

// Chamfer distance, B=16, N=M=2048, D=4, fp32 — ONE kernel, one matrix pass.
//   dist2[b,i,j] = cp_j - 2 y_j . x_i + cq_i    (eps 1e-12 negligible)
// Block = (batch, 16-column tile of y); 256 threads x 8 x-rows/thread
// (4 fma.rn.f32x2 packs). Row mins: s = cp - 2p.q, cq folded post-loop.
// Col mins: sc = s + cq (packed add) -> cmin[16] regs -> warp fold+transpose
// (lane L<16 owns col L) -> 1 REDG per low lane.
// Cross-block min: atomicMax on ~bits(clamped dist2); zero key == +inf ->
// no init needed. Last block (global ticket) reads 256 KB of keys, sqrts,
// fixed-order sums -> out; resets keys + counter for graph replay.
// All reductions order-independent or fixed-order -> deterministic.

#define BATCH    16
#define NP       2048
#define THREADS  256
#define QPT      8                           // x-rows per thread (4 packs)
#define NPACK    (QPT / 2)                   // 4
#define PTS      16                          // y-columns per block
#define TJ       (NP / PTS)                  // 128 column tiles
#define NBLK     (BATCH * TJ)                // 2048 blocks
#define NQTOT    (BATCH * 2 * NP)            // 65536 keys (x side + y side)

__device__ unsigned int g_key[NQTOT];        // ~bits(dist^2); 0 == +inf
__device__ unsigned int g_count;             // zero-init; self-resetting

// ---- packed f32x2 helpers -------------------------------------------------
__device__ __forceinline__ unsigned long long pk2(float lo, float hi) {
    unsigned long long r;
    asm("mov.b64 %0, {%1, %2};" : "=l"(r) : "f"(lo), "f"(hi));
    return r;
}
__device__ __forceinline__ void upk2(unsigned long long v, float& lo, float& hi) {
    asm("mov.b64 {%0, %1}, %2;" : "=f"(lo), "=f"(hi) : "l"(v));
}
__device__ __forceinline__ unsigned long long fma2(unsigned long long a,
                                                   unsigned long long b,
                                                   unsigned long long c) {
    unsigned long long d;
    asm("fma.rn.f32x2 %0, %1, %2, %3;" : "=l"(d) : "l"(a), "l"(b), "l"(c));
    return d;
}
__device__ __forceinline__ unsigned long long add2(unsigned long long a,
                                                   unsigned long long b) {
    unsigned long long d;
    asm("add.rn.f32x2 %0, %1, %2;" : "=l"(d) : "l"(a), "l"(b));
    return d;
}

// ---- fused kernel ---------------------------------------------------------
extern "C" __global__ void __launch_bounds__(THREADS, 3)
chamfer_fused(const float* __restrict__ x, const float* __restrict__ y,
              float* __restrict__ out)
{
    const int bid = blockIdx.x;
    const int tj  = bid & (TJ - 1);
    const int b   = bid >> 7;

    const float4* xb = (const float4*)(x + (size_t)b * NP * 4);
    const float4* yb = (const float4*)(y + (size_t)b * NP * 4);

    __shared__ float4 arrA[PTS];   // (-2p.x,-2p.x,-2p.y,-2p.y)
    __shared__ float4 arrB[PTS];   // (-2p.z,-2p.z,-2p.w,-2p.w)
    __shared__ float2 arrC[PTS];   // (cp, cp)
    __shared__ float  red[THREADS];
    __shared__ int    flag;

    const int tid = threadIdx.x;

    if (tid < PTS) {
        float4 p = yb[tj * PTS + tid];
        float cp = p.x * p.x + p.y * p.y + p.z * p.z + p.w * p.w;
        arrA[tid] = make_float4(-2.f * p.x, -2.f * p.x, -2.f * p.y, -2.f * p.y);
        arrB[tid] = make_float4(-2.f * p.z, -2.f * p.z, -2.f * p.w, -2.f * p.w);
        arrC[tid] = make_float2(cp, cp);
    }

    // 8 x-rows, packed pairwise; cq packed alongside
    unsigned long long a0[NPACK], a1[NPACK], a2[NPACK], a3[NPACK], cq2[NPACK];
#pragma unroll
    for (int p = 0; p < NPACK; p++) {
        float4 u = xb[(2 * p)     * THREADS + tid];
        float4 v = xb[(2 * p + 1) * THREADS + tid];
        a0[p] = pk2(u.x, v.x);
        a1[p] = pk2(u.y, v.y);
        a2[p] = pk2(u.z, v.z);
        a3[p] = pk2(u.w, v.w);
        cq2[p] = pk2(u.x*u.x + u.y*u.y + u.z*u.z + u.w*u.w,
                     v.x*v.x + v.y*v.y + v.z*v.z + v.w*v.w);
    }

    float m[QPT];
#pragma unroll
    for (int i = 0; i < QPT; i++) m[i] = FLT_MAX;
    float cmin[PTS];
#pragma unroll
    for (int j = 0; j < PTS; j++) cmin[j] = FLT_MAX;

    __syncthreads();

    const ulonglong2* A = (const ulonglong2*)arrA;
    const ulonglong2* B = (const ulonglong2*)arrB;
    const unsigned long long* C = (const unsigned long long*)arrC;

#pragma unroll 4
    for (int j = 0; j < PTS; j++) {
        ulonglong2 va = A[j];                // broadcast LDS.128
        ulonglong2 vb = B[j];                // broadcast LDS.128
        unsigned long long vc = C[j];        // broadcast LDS.64
        float cmj = cmin[j];
#pragma unroll
        for (int p = 0; p < NPACK; p++) {
            unsigned long long s = fma2(va.x, a0[p], vc);
            s = fma2(va.y, a1[p], s);
            s = fma2(vb.x, a2[p], s);
            s = fma2(vb.y, a3[p], s);        // s = cp - 2 p.q
            unsigned long long sc = add2(s, cq2[p]);  // full dist^2
            float s0, s1, c0, c1;
            upk2(s, s0, s1);
            upk2(sc, c0, c1);
            m[2*p]   = fminf(m[2*p],   s0);  // row mins (alu pipe)
            m[2*p+1] = fminf(m[2*p+1], s1);
            cmj = fminf(cmj, fminf(c0, c1)); // col min
        }
        cmin[j] = cmj;
    }

    // ---- row epilogue: fold cq, clamp, RED.MAX on complemented bits ----
#pragma unroll
    for (int p = 0; p < NPACK; p++) {
        float cq0, cq1;
        upk2(cq2[p], cq0, cq1);
        float d0 = fmaxf(m[2*p]   + cq0, 0.f);
        float d1 = fmaxf(m[2*p+1] + cq1, 0.f);
        atomicMax(&g_key[b * NP + (2 * p)     * THREADS + tid], ~__float_as_uint(d0));
        atomicMax(&g_key[b * NP + (2 * p + 1) * THREADS + tid], ~__float_as_uint(d1));
    }

    // ---- col epilogue: fold bit-16 lanes, then 16-reg transpose-reduce ----
    const int lane = tid & 31;
#pragma unroll
    for (int k = 0; k < PTS; k++)
        cmin[k] = fminf(cmin[k], __shfl_xor_sync(0xffffffffu, cmin[k], 16));
#pragma unroll
    for (int off = 8; off >= 1; off >>= 1) {
#pragma unroll
        for (int k = 0; k < off; k++) {
            float mine   = (lane & off) ? cmin[k + off] : cmin[k];
            float theirs = (lane & off) ? cmin[k]       : cmin[k + off];
            float got = __shfl_xor_sync(0xffffffffu, theirs, off);
            cmin[k] = fminf(mine, got);
        }
    }
    if (lane < 16) {
        float dcol = fmaxf(cmin[0], 0.f);    // col (lane) min over this warp
        atomicMax(&g_key[BATCH * NP + b * NP + tj * PTS + lane],
                  ~__float_as_uint(dcol));
    }

    // ---- global ticket: last block finishes -------------------------------
    __threadfence();
    if (tid == 0) {
        unsigned int v = atomicAdd(&g_count, 1u);
        flag = (v == NBLK - 1);
    }
    __syncthreads();
    if (!flag) return;

    __threadfence();                         // acquire all key updates
    float acc = 0.f;
    uint4* k4 = (uint4*)g_key;
#pragma unroll 4
    for (int i = tid; i < NQTOT / 4; i += THREADS) {
        uint4 k = k4[i];
        k4[i] = make_uint4(0u, 0u, 0u, 0u);  // reset (= +inf) for replay
        acc += sqrtf(__uint_as_float(~k.x)) + sqrtf(__uint_as_float(~k.y))
             + sqrtf(__uint_as_float(~k.z)) + sqrtf(__uint_as_float(~k.w));
    }

    red[tid] = acc;
    __syncthreads();
#pragma unroll
    for (int s = THREADS / 2; s > 0; s >>= 1) {
        if (tid < s) red[tid] += red[tid + s];
        __syncthreads();
    }
    if (tid == 0) {
        out[0] = red[0];
        __threadfence();
        g_count = 0;                         // reset for graph replay
    }
}

// ---- launch ---------------------------------------------------------------
extern "C" void kernel_launch(void* const* d_in, const int* in_sizes, int n_in,
                              void* d_out, int out_size)
{
    const float* x = (const float*)d_in[0];
    const float* y = (const float*)d_in[1];
    float* out = (float*)d_out;

    chamfer_fused<<<NBLK, THREADS>>>(x, y, out);
}

// round 12
// speedup vs baseline: 1.1079x; 1.1079x over previous
#include <cuda_runtime.h>
#include <math.h>
#include <float.h>

// Chamfer distance, B=16, N=M=2048, D=4, fp32 — ONE kernel, one matrix pass.
//   dist2[b,i,j] = cp_j - 2 y_j . x_i + cq_i    (eps 1e-12 negligible)
// Block = (batch, 32-column tile of y); 256 threads x 8 x-rows/thread
// (4 fma.rn.f32x2 packs). Row mins: s = cp - 2p.q, cq folded post-loop.
// Col mins: sc = s + cq (packed add) -> cmin[32] regs -> warp transpose-
// reduce (lane L owns col L) -> 1 RED per lane. Inner loop uses explicit
// 1-deep SMEM prefetch (padded arrays) to hide LDS latency.
// Cross-block min: atomicMax on ~bits(clamped dist2); zero key == +inf ->
// no init kernel. Last block (global ticket) reads 256 KB of keys, sqrts,
// fixed-order sums -> out; resets keys + counter for graph replay.
// All reductions order-independent or fixed-order -> deterministic.

#define BATCH    16
#define NP       2048
#define THREADS  256
#define QPT      8                           // x-rows per thread (4 packs)
#define NPACK    (QPT / 2)                   // 4
#define PTS      32                          // y-columns per block
#define TJ       (NP / PTS)                  // 64 column tiles
#define NBLK     (BATCH * TJ)                // 1024 blocks
#define NQTOT    (BATCH * 2 * NP)            // 65536 keys (x side + y side)

__device__ unsigned int g_key[NQTOT];        // ~bits(dist^2); 0 == +inf
__device__ unsigned int g_count;             // zero-init; self-resetting

// ---- packed f32x2 helpers -------------------------------------------------
__device__ __forceinline__ unsigned long long pk2(float lo, float hi) {
    unsigned long long r;
    asm("mov.b64 %0, {%1, %2};" : "=l"(r) : "f"(lo), "f"(hi));
    return r;
}
__device__ __forceinline__ void upk2(unsigned long long v, float& lo, float& hi) {
    asm("mov.b64 {%0, %1}, %2;" : "=f"(lo), "=f"(hi) : "l"(v));
}
__device__ __forceinline__ unsigned long long fma2(unsigned long long a,
                                                   unsigned long long b,
                                                   unsigned long long c) {
    unsigned long long d;
    asm("fma.rn.f32x2 %0, %1, %2, %3;" : "=l"(d) : "l"(a), "l"(b), "l"(c));
    return d;
}
__device__ __forceinline__ unsigned long long add2(unsigned long long a,
                                                   unsigned long long b) {
    unsigned long long d;
    asm("add.rn.f32x2 %0, %1, %2;" : "=l"(d) : "l"(a), "l"(b));
    return d;
}

// ---- fused kernel ---------------------------------------------------------
extern "C" __global__ void __launch_bounds__(THREADS, 2)
chamfer_fused(const float* __restrict__ x, const float* __restrict__ y,
              float* __restrict__ out)
{
    const int bid = blockIdx.x;
    const int tj  = bid & (TJ - 1);
    const int b   = bid >> 6;

    const float4* xb = (const float4*)(x + (size_t)b * NP * 4);
    const float4* yb = (const float4*)(y + (size_t)b * NP * 4);

    __shared__ float4 arrA[PTS + 1];   // (-2p.x,-2p.x,-2p.y,-2p.y)  (+1 pad)
    __shared__ float4 arrB[PTS + 1];   // (-2p.z,-2p.z,-2p.w,-2p.w)
    __shared__ float2 arrC[PTS + 1];   // (cp, cp)
    __shared__ float  red[THREADS];
    __shared__ int    flag;

    const int tid = threadIdx.x;

    if (tid < PTS) {
        float4 p = yb[tj * PTS + tid];
        float cp = p.x * p.x + p.y * p.y + p.z * p.z + p.w * p.w;
        arrA[tid] = make_float4(-2.f * p.x, -2.f * p.x, -2.f * p.y, -2.f * p.y);
        arrB[tid] = make_float4(-2.f * p.z, -2.f * p.z, -2.f * p.w, -2.f * p.w);
        arrC[tid] = make_float2(cp, cp);
    }
    if (tid == PTS) {                        // pad entry (read by prefetch,
        arrA[PTS] = make_float4(0.f, 0.f, 0.f, 0.f);  // never consumed)
        arrB[PTS] = make_float4(0.f, 0.f, 0.f, 0.f);
        arrC[PTS] = make_float2(0.f, 0.f);
    }

    // 8 x-rows, packed pairwise; cq packed alongside
    unsigned long long a0[NPACK], a1[NPACK], a2[NPACK], a3[NPACK], cq2[NPACK];
#pragma unroll
    for (int p = 0; p < NPACK; p++) {
        float4 u = xb[(2 * p)     * THREADS + tid];
        float4 v = xb[(2 * p + 1) * THREADS + tid];
        a0[p] = pk2(u.x, v.x);
        a1[p] = pk2(u.y, v.y);
        a2[p] = pk2(u.z, v.z);
        a3[p] = pk2(u.w, v.w);
        cq2[p] = pk2(u.x*u.x + u.y*u.y + u.z*u.z + u.w*u.w,
                     v.x*v.x + v.y*v.y + v.z*v.z + v.w*v.w);
    }

    float m[QPT];
#pragma unroll
    for (int i = 0; i < QPT; i++) m[i] = FLT_MAX;
    float cmin[PTS];
#pragma unroll
    for (int j = 0; j < PTS; j++) cmin[j] = FLT_MAX;

    __syncthreads();

    const ulonglong2* A = (const ulonglong2*)arrA;
    const ulonglong2* B = (const ulonglong2*)arrB;
    const unsigned long long* C = (const unsigned long long*)arrC;

    // 1-deep software pipeline: LDS for j+1 issues before computing j
    ulonglong2 va = A[0];
    ulonglong2 vb = B[0];
    unsigned long long vc = C[0];
#pragma unroll 4
    for (int j = 0; j < PTS; j++) {
        ulonglong2 va_n = A[j + 1];          // broadcast LDS.128 (pad-safe)
        ulonglong2 vb_n = B[j + 1];
        unsigned long long vc_n = C[j + 1];
        float cmj = cmin[j];
#pragma unroll
        for (int p = 0; p < NPACK; p++) {
            unsigned long long s = fma2(va.x, a0[p], vc);
            s = fma2(va.y, a1[p], s);
            s = fma2(vb.x, a2[p], s);
            s = fma2(vb.y, a3[p], s);        // s = cp - 2 p.q
            unsigned long long sc = add2(s, cq2[p]);  // full dist^2
            float s0, s1, c0, c1;
            upk2(s, s0, s1);
            upk2(sc, c0, c1);
            m[2*p]   = fminf(m[2*p],   s0);  // row mins (alu pipe)
            m[2*p+1] = fminf(m[2*p+1], s1);
            cmj = fminf(cmj, fminf(c0, c1)); // col min
        }
        cmin[j] = cmj;
        va = va_n; vb = vb_n; vc = vc_n;
    }

    // ---- row epilogue: fold cq, clamp, RED.MAX on complemented bits ----
#pragma unroll
    for (int p = 0; p < NPACK; p++) {
        float cq0, cq1;
        upk2(cq2[p], cq0, cq1);
        float d0 = fmaxf(m[2*p]   + cq0, 0.f);
        float d1 = fmaxf(m[2*p+1] + cq1, 0.f);
        atomicMax(&g_key[b * NP + (2 * p)     * THREADS + tid], ~__float_as_uint(d0));
        atomicMax(&g_key[b * NP + (2 * p + 1) * THREADS + tid], ~__float_as_uint(d1));
    }

    // ---- col epilogue: inter-lane transpose-reduce, lane L owns col L ----
    const int lane = tid & 31;
#pragma unroll
    for (int off = 16; off >= 1; off >>= 1) {
#pragma unroll
        for (int k = 0; k < off; k++) {
            float mine   = (lane & off) ? cmin[k + off] : cmin[k];
            float theirs = (lane & off) ? cmin[k]       : cmin[k + off];
            float got = __shfl_xor_sync(0xffffffffu, theirs, off);
            cmin[k] = fminf(mine, got);
        }
    }
    float dcol = fmaxf(cmin[0], 0.f);        // this warp's min for column `lane`
    atomicMax(&g_key[BATCH * NP + b * NP + tj * PTS + lane], ~__float_as_uint(dcol));

    // ---- global ticket: last block finishes -------------------------------
    __threadfence();
    if (tid == 0) {
        unsigned int v = atomicAdd(&g_count, 1u);
        flag = (v == NBLK - 1);
    }
    __syncthreads();
    if (!flag) return;

    __threadfence();                         // acquire all key updates
    float acc = 0.f;
    uint4* k4 = (uint4*)g_key;
#pragma unroll 4
    for (int i = tid; i < NQTOT / 4; i += THREADS) {
        uint4 k = k4[i];
        k4[i] = make_uint4(0u, 0u, 0u, 0u);  // reset (= +inf) for replay
        acc += sqrtf(__uint_as_float(~k.x)) + sqrtf(__uint_as_float(~k.y))
             + sqrtf(__uint_as_float(~k.z)) + sqrtf(__uint_as_float(~k.w));
    }

    red[tid] = acc;
    __syncthreads();
#pragma unroll
    for (int s = THREADS / 2; s > 0; s >>= 1) {
        if (tid < s) red[tid] += red[tid + s];
        __syncthreads();
    }
    if (tid == 0) {
        out[0] = red[0];
        __threadfence();
        g_count = 0;                         // reset for graph replay
    }
}

// ---- launch ---------------------------------------------------------------
extern "C" void kernel_launch(void* const* d_in, const int* in_sizes, int n_in,
                              void* d_out, int out_size)
{
    const float* x = (const float*)d_in[0];
    const float* y = (const float*)d_in[1];
    float* out = (float*)d_out;

    chamfer_fused<<<NBLK, THREADS>>>(x, y, out);
}

// round 15
// speedup vs baseline: 1.9124x; 1.7261x over previous
#include <cuda_runtime.h>
#include <math.h>
#include <float.h>

// Chamfer distance, B=16, N=M=2048, D=4, fp32 — two kernels, one matrix pass.
//   dist2[b,i,j] = (cp_j - 2 y_j . x_i) + cq_i   (eps 1e-12 negligible)
// Main: block = (batch, 32-col tile of y); 256 thr x 8 x-rows (4 f32x2 packs).
// Both row and col mins accumulate on the SAME unpacked dist2 values
// (min_j(s+cq) = min_j(s)+cq, so no separate row path -> fewer MOV/FMNMX).
// Col mins -> cmin[32] regs -> warp transpose-reduce (lane L owns col L).
// Cross-block min: atomicMax on ~bits(clamped dist2); zero key == +inf ->
// no init kernel. Combine: 64x256, uint4 keys, sqrt, fixed-order sums,
// resets keys for graph replay. Deterministic throughout.

#define BATCH    16
#define NP       2048
#define THREADS  256
#define QPT      8                           // x-rows per thread (4 packs)
#define NPACK    (QPT / 2)                   // 4
#define PTS      32                          // y-columns per block
#define TJ       (NP / PTS)                  // 64 column tiles
#define NBLK     (BATCH * TJ)                // 1024 blocks
#define NQTOT    (BATCH * 2 * NP)            // 65536 keys (x side + y side)
#define CBLK     64
#define CTHR     256

__device__ unsigned int g_key[NQTOT];        // ~bits(dist^2); 0 == +inf
__device__ float g_psum[CBLK];
__device__ unsigned int g_count;             // zero-init; self-resetting

// ---- packed f32x2 helpers -------------------------------------------------
__device__ __forceinline__ unsigned long long pk2(float lo, float hi) {
    unsigned long long r;
    asm("mov.b64 %0, {%1, %2};" : "=l"(r) : "f"(lo), "f"(hi));
    return r;
}
__device__ __forceinline__ void upk2(unsigned long long v, float& lo, float& hi) {
    asm("mov.b64 {%0, %1}, %2;" : "=f"(lo), "=f"(hi) : "l"(v));
}
__device__ __forceinline__ unsigned long long fma2(unsigned long long a,
                                                   unsigned long long b,
                                                   unsigned long long c) {
    unsigned long long d;
    asm("fma.rn.f32x2 %0, %1, %2, %3;" : "=l"(d) : "l"(a), "l"(b), "l"(c));
    return d;
}
__device__ __forceinline__ unsigned long long add2(unsigned long long a,
                                                   unsigned long long b) {
    unsigned long long d;
    asm("add.rn.f32x2 %0, %1, %2;" : "=l"(d) : "l"(a), "l"(b));
    return d;
}

// ---- main kernel ----------------------------------------------------------
extern "C" __global__ void __launch_bounds__(THREADS, 2)
chamfer_main(const float* __restrict__ x, const float* __restrict__ y)
{
    const int bid = blockIdx.x;
    const int tj  = bid & (TJ - 1);
    const int b   = bid >> 6;

    const float4* xb = (const float4*)(x + (size_t)b * NP * 4);
    const float4* yb = (const float4*)(y + (size_t)b * NP * 4);

    __shared__ float4 arrA[PTS];   // (-2p.x,-2p.x,-2p.y,-2p.y)
    __shared__ float4 arrB[PTS];   // (-2p.z,-2p.z,-2p.w,-2p.w)
    __shared__ float2 arrC[PTS];   // (cp, cp)

    const int tid = threadIdx.x;

    if (tid < PTS) {
        float4 p = yb[tj * PTS + tid];
        float cp = p.x * p.x + p.y * p.y + p.z * p.z + p.w * p.w;
        arrA[tid] = make_float4(-2.f * p.x, -2.f * p.x, -2.f * p.y, -2.f * p.y);
        arrB[tid] = make_float4(-2.f * p.z, -2.f * p.z, -2.f * p.w, -2.f * p.w);
        arrC[tid] = make_float2(cp, cp);
    }

    // 8 x-rows, packed pairwise; cq packed alongside
    unsigned long long a0[NPACK], a1[NPACK], a2[NPACK], a3[NPACK], cq2[NPACK];
#pragma unroll
    for (int p = 0; p < NPACK; p++) {
        float4 u = xb[(2 * p)     * THREADS + tid];
        float4 v = xb[(2 * p + 1) * THREADS + tid];
        a0[p] = pk2(u.x, v.x);
        a1[p] = pk2(u.y, v.y);
        a2[p] = pk2(u.z, v.z);
        a3[p] = pk2(u.w, v.w);
        cq2[p] = pk2(u.x*u.x + u.y*u.y + u.z*u.z + u.w*u.w,
                     v.x*v.x + v.y*v.y + v.z*v.z + v.w*v.w);
    }

    float m[QPT];                            // row mins of FULL dist^2
#pragma unroll
    for (int i = 0; i < QPT; i++) m[i] = FLT_MAX;
    float cmin[PTS];                         // col mins of FULL dist^2
#pragma unroll
    for (int j = 0; j < PTS; j++) cmin[j] = FLT_MAX;

    __syncthreads();

    const ulonglong2* A = (const ulonglong2*)arrA;
    const ulonglong2* B = (const ulonglong2*)arrB;
    const unsigned long long* C = (const unsigned long long*)arrC;

#pragma unroll 4
    for (int j = 0; j < PTS; j++) {
        ulonglong2 va = A[j];                // broadcast LDS.128
        ulonglong2 vb = B[j];                // broadcast LDS.128
        unsigned long long vc = C[j];        // broadcast LDS.64
        float cmj = cmin[j];
#pragma unroll
        for (int p = 0; p < NPACK; p++) {
            unsigned long long s = fma2(va.x, a0[p], vc);
            s = fma2(va.y, a1[p], s);
            s = fma2(vb.x, a2[p], s);
            s = fma2(vb.y, a3[p], s);        // cp - 2 p.q
            s = add2(s, cq2[p]);             // full dist^2
            float c0, c1;
            upk2(s, c0, c1);                 // ONE unpack feeds both reductions
            m[2*p]   = fminf(m[2*p],   c0);  // row mins
            m[2*p+1] = fminf(m[2*p+1], c1);
            cmj = fminf(cmj, fminf(c0, c1)); // col min
        }
        cmin[j] = cmj;
    }

    // ---- row epilogue: clamp, RED.MAX on complemented bits ----
#pragma unroll
    for (int p = 0; p < NPACK; p++) {
        float d0 = fmaxf(m[2*p],   0.f);
        float d1 = fmaxf(m[2*p+1], 0.f);
        atomicMax(&g_key[b * NP + (2 * p)     * THREADS + tid], ~__float_as_uint(d0));
        atomicMax(&g_key[b * NP + (2 * p + 1) * THREADS + tid], ~__float_as_uint(d1));
    }

    // ---- col epilogue: inter-lane transpose-reduce, lane L owns col L ----
    const int lane = tid & 31;
#pragma unroll
    for (int off = 16; off >= 1; off >>= 1) {
#pragma unroll
        for (int k = 0; k < off; k++) {
            float mine   = (lane & off) ? cmin[k + off] : cmin[k];
            float theirs = (lane & off) ? cmin[k]       : cmin[k + off];
            float got = __shfl_xor_sync(0xffffffffu, theirs, off);
            cmin[k] = fminf(mine, got);
        }
    }
    float dcol = fmaxf(cmin[0], 0.f);        // this warp's min for column `lane`
    atomicMax(&g_key[BATCH * NP + b * NP + tj * PTS + lane], ~__float_as_uint(dcol));
}

// ---- combine: sqrt + deterministic sum; resets keys; last block finishes --
extern "C" __global__ void __launch_bounds__(CTHR)
chamfer_combine(float* __restrict__ out)
{
    const int base = (blockIdx.x * CTHR + threadIdx.x) * 4;
    uint4 k = *(const uint4*)&g_key[base];
    *(uint4*)&g_key[base] = make_uint4(0u, 0u, 0u, 0u);  // reset for replay
    float d = sqrtf(__uint_as_float(~k.x)) + sqrtf(__uint_as_float(~k.y))
            + sqrtf(__uint_as_float(~k.z)) + sqrtf(__uint_as_float(~k.w));

    __shared__ float red[CTHR];
    red[threadIdx.x] = d;
    __syncthreads();
#pragma unroll
    for (int s = CTHR / 2; s > 0; s >>= 1) {
        if (threadIdx.x < s) red[threadIdx.x] += red[threadIdx.x + s];
        __syncthreads();
    }

    __shared__ int is_last;
    if (threadIdx.x == 0) {
        g_psum[blockIdx.x] = red[0];
        __threadfence();
        unsigned int c = atomicAdd(&g_count, 1u);
        is_last = (c == CBLK - 1);
    }
    __syncthreads();

    if (is_last && threadIdx.x == 0) {
        __threadfence();
        float t = 0.f;
#pragma unroll
        for (int i = 0; i < CBLK; i++) t += g_psum[i];   // fixed order
        out[0] = t;
        __threadfence();
        g_count = 0;                       // reset for graph replay
    }
}

// ---- launch ---------------------------------------------------------------
extern "C" void kernel_launch(void* const* d_in, const int* in_sizes, int n_in,
                              void* d_out, int out_size)
{
    const float* x = (const float*)d_in[0];
    const float* y = (const float*)d_in[1];
    float* out = (float*)d_out;

    chamfer_main<<<NBLK, THREADS>>>(x, y);
    chamfer_combine<<<CBLK, CTHR>>>(out);
}

// round 16
// speedup vs baseline: 1.9713x; 1.0308x over previous
#include <cuda_runtime.h>
#include <math.h>
#include <float.h>

// Chamfer distance, B=16, N=M=2048, D=4, fp32 — two kernels, one matrix pass.
//   dist2[b,i,j] = (cp_j - 2 y_j . x_i) + cq_i   (eps 1e-12 negligible)
// Main (FROZEN from R15 win): block = (batch, 32-col tile of y); 256 thr x
// 8 x-rows (4 f32x2 packs). Row and col mins accumulate on the SAME unpacked
// dist2 values. Col mins -> warp transpose-reduce. Cross-block min: atomicMax
// on ~bits(clamped dist2); zero key == +inf -> no init kernel.
// Combine (NEW): 32 blocks x 128 thr x 4 uint4/thread (MLP=4 coalesced),
// warp-shuffle reduce + 4-entry smem fold, fixed-order ticket finish;
// resets keys for graph replay. Deterministic throughout.

#define BATCH    16
#define NP       2048
#define THREADS  256
#define QPT      8                           // x-rows per thread (4 packs)
#define NPACK    (QPT / 2)                   // 4
#define PTS      32                          // y-columns per block
#define TJ       (NP / PTS)                  // 64 column tiles
#define NBLK     (BATCH * TJ)                // 1024 blocks
#define NQTOT    (BATCH * 2 * NP)            // 65536 keys (x side + y side)
#define CBLK     32
#define CTHR     128
#define CV       4                           // uint4 loads per combine thread

__device__ unsigned int g_key[NQTOT];        // ~bits(dist^2); 0 == +inf
__device__ float g_psum[CBLK];
__device__ unsigned int g_count;             // zero-init; self-resetting

// ---- packed f32x2 helpers -------------------------------------------------
__device__ __forceinline__ unsigned long long pk2(float lo, float hi) {
    unsigned long long r;
    asm("mov.b64 %0, {%1, %2};" : "=l"(r) : "f"(lo), "f"(hi));
    return r;
}
__device__ __forceinline__ void upk2(unsigned long long v, float& lo, float& hi) {
    asm("mov.b64 {%0, %1}, %2;" : "=f"(lo), "=f"(hi) : "l"(v));
}
__device__ __forceinline__ unsigned long long fma2(unsigned long long a,
                                                   unsigned long long b,
                                                   unsigned long long c) {
    unsigned long long d;
    asm("fma.rn.f32x2 %0, %1, %2, %3;" : "=l"(d) : "l"(a), "l"(b), "l"(c));
    return d;
}
__device__ __forceinline__ unsigned long long add2(unsigned long long a,
                                                   unsigned long long b) {
    unsigned long long d;
    asm("add.rn.f32x2 %0, %1, %2;" : "=l"(d) : "l"(a), "l"(b));
    return d;
}

// ---- main kernel (unchanged from R15) -------------------------------------
extern "C" __global__ void __launch_bounds__(THREADS, 2)
chamfer_main(const float* __restrict__ x, const float* __restrict__ y)
{
    const int bid = blockIdx.x;
    const int tj  = bid & (TJ - 1);
    const int b   = bid >> 6;

    const float4* xb = (const float4*)(x + (size_t)b * NP * 4);
    const float4* yb = (const float4*)(y + (size_t)b * NP * 4);

    __shared__ float4 arrA[PTS];   // (-2p.x,-2p.x,-2p.y,-2p.y)
    __shared__ float4 arrB[PTS];   // (-2p.z,-2p.z,-2p.w,-2p.w)
    __shared__ float2 arrC[PTS];   // (cp, cp)

    const int tid = threadIdx.x;

    if (tid < PTS) {
        float4 p = yb[tj * PTS + tid];
        float cp = p.x * p.x + p.y * p.y + p.z * p.z + p.w * p.w;
        arrA[tid] = make_float4(-2.f * p.x, -2.f * p.x, -2.f * p.y, -2.f * p.y);
        arrB[tid] = make_float4(-2.f * p.z, -2.f * p.z, -2.f * p.w, -2.f * p.w);
        arrC[tid] = make_float2(cp, cp);
    }

    // 8 x-rows, packed pairwise; cq packed alongside
    unsigned long long a0[NPACK], a1[NPACK], a2[NPACK], a3[NPACK], cq2[NPACK];
#pragma unroll
    for (int p = 0; p < NPACK; p++) {
        float4 u = xb[(2 * p)     * THREADS + tid];
        float4 v = xb[(2 * p + 1) * THREADS + tid];
        a0[p] = pk2(u.x, v.x);
        a1[p] = pk2(u.y, v.y);
        a2[p] = pk2(u.z, v.z);
        a3[p] = pk2(u.w, v.w);
        cq2[p] = pk2(u.x*u.x + u.y*u.y + u.z*u.z + u.w*u.w,
                     v.x*v.x + v.y*v.y + v.z*v.z + v.w*v.w);
    }

    float m[QPT];                            // row mins of FULL dist^2
#pragma unroll
    for (int i = 0; i < QPT; i++) m[i] = FLT_MAX;
    float cmin[PTS];                         // col mins of FULL dist^2
#pragma unroll
    for (int j = 0; j < PTS; j++) cmin[j] = FLT_MAX;

    __syncthreads();

    const ulonglong2* A = (const ulonglong2*)arrA;
    const ulonglong2* B = (const ulonglong2*)arrB;
    const unsigned long long* C = (const unsigned long long*)arrC;

#pragma unroll 4
    for (int j = 0; j < PTS; j++) {
        ulonglong2 va = A[j];                // broadcast LDS.128
        ulonglong2 vb = B[j];                // broadcast LDS.128
        unsigned long long vc = C[j];        // broadcast LDS.64
        float cmj = cmin[j];
#pragma unroll
        for (int p = 0; p < NPACK; p++) {
            unsigned long long s = fma2(va.x, a0[p], vc);
            s = fma2(va.y, a1[p], s);
            s = fma2(vb.x, a2[p], s);
            s = fma2(vb.y, a3[p], s);        // cp - 2 p.q
            s = add2(s, cq2[p]);             // full dist^2
            float c0, c1;
            upk2(s, c0, c1);                 // ONE unpack feeds both reductions
            m[2*p]   = fminf(m[2*p],   c0);  // row mins
            m[2*p+1] = fminf(m[2*p+1], c1);
            cmj = fminf(cmj, fminf(c0, c1)); // col min
        }
        cmin[j] = cmj;
    }

    // ---- row epilogue: clamp, RED.MAX on complemented bits ----
#pragma unroll
    for (int p = 0; p < NPACK; p++) {
        float d0 = fmaxf(m[2*p],   0.f);
        float d1 = fmaxf(m[2*p+1], 0.f);
        atomicMax(&g_key[b * NP + (2 * p)     * THREADS + tid], ~__float_as_uint(d0));
        atomicMax(&g_key[b * NP + (2 * p + 1) * THREADS + tid], ~__float_as_uint(d1));
    }

    // ---- col epilogue: inter-lane transpose-reduce, lane L owns col L ----
    const int lane = tid & 31;
#pragma unroll
    for (int off = 16; off >= 1; off >>= 1) {
#pragma unroll
        for (int k = 0; k < off; k++) {
            float mine   = (lane & off) ? cmin[k + off] : cmin[k];
            float theirs = (lane & off) ? cmin[k]       : cmin[k + off];
            float got = __shfl_xor_sync(0xffffffffu, theirs, off);
            cmin[k] = fminf(mine, got);
        }
    }
    float dcol = fmaxf(cmin[0], 0.f);        // this warp's min for column `lane`
    atomicMax(&g_key[BATCH * NP + b * NP + tj * PTS + lane], ~__float_as_uint(dcol));
}

// ---- combine: MLP-4 key read, sqrt, warp reduce, ticket finish ------------
extern "C" __global__ void __launch_bounds__(CTHR)
chamfer_combine(float* __restrict__ out)
{
    const int tid = threadIdx.x;
    uint4* k4 = (uint4*)g_key;

    // 4 coalesced uint4 loads per thread (independent -> MLP=4)
    uint4 k[CV];
#pragma unroll
    for (int i = 0; i < CV; i++)
        k[i] = k4[blockIdx.x * CTHR * CV + i * CTHR + tid];
#pragma unroll
    for (int i = 0; i < CV; i++)
        k4[blockIdx.x * CTHR * CV + i * CTHR + tid] = make_uint4(0u, 0u, 0u, 0u);

    float acc = 0.f;
#pragma unroll
    for (int i = 0; i < CV; i++) {
        acc += sqrtf(__uint_as_float(~k[i].x)) + sqrtf(__uint_as_float(~k[i].y))
             + sqrtf(__uint_as_float(~k[i].z)) + sqrtf(__uint_as_float(~k[i].w));
    }

    // warp shuffle reduce (fixed butterfly order -> deterministic)
#pragma unroll
    for (int off = 16; off >= 1; off >>= 1)
        acc += __shfl_xor_sync(0xffffffffu, acc, off);

    __shared__ float wsum[CTHR / 32];
    __shared__ int is_last;
    if ((tid & 31) == 0) wsum[tid >> 5] = acc;
    __syncthreads();

    if (tid == 0) {
        float bsum = wsum[0] + wsum[1] + wsum[2] + wsum[3];  // fixed order
        g_psum[blockIdx.x] = bsum;
        __threadfence();
        unsigned int c = atomicAdd(&g_count, 1u);
        is_last = (c == CBLK - 1);
    }
    __syncthreads();

    if (is_last && tid == 0) {
        __threadfence();
        float t = 0.f;
#pragma unroll
        for (int i = 0; i < CBLK; i++) t += g_psum[i];       // fixed order
        out[0] = t;
        __threadfence();
        g_count = 0;                       // reset for graph replay
    }
}

// ---- launch ---------------------------------------------------------------
extern "C" void kernel_launch(void* const* d_in, const int* in_sizes, int n_in,
                              void* d_out, int out_size)
{
    const float* x = (const float*)d_in[0];
    const float* y = (const float*)d_in[1];
    float* out = (float*)d_out;

    chamfer_main<<<NBLK, THREADS>>>(x, y);
    chamfer_combine<<<CBLK, CTHR>>>(out);
}